// round 1
// baseline (speedup 1.0000x reference)
#include <cuda_runtime.h>

#define BATCH  16
#define H      1024
#define W      1024
#define HW     (H*W)
#define STRIP  224
#define SEG    256
#define NSTRIP 5        // 5*224 = 1120 >= 1024
#define CHUNK  128
#define NCHUNK 8

__device__ float g_accum[BATCH * 5];

__global__ void zero_kernel() {
    int i = threadIdx.x;
    if (i < BATCH * 5) g_accum[i] = 0.f;
}

__global__ __launch_bounds__(256) void adaptive_loss_main(
    const float* __restrict__ pred, const float* __restrict__ mask)
{
    __shared__ float Pl[32][SEG];   // ring of row prefix sums (rows y-16 .. y+15)
    __shared__ float wsum[8];
    __shared__ float red[8][5];

    const int tid  = threadIdx.x;
    const int lane = tid & 31;
    const int warp = tid >> 5;

    const int bid = blockIdx.x;
    const int b   = bid / (NSTRIP * NCHUNK);
    const int rem = bid % (NSTRIP * NCHUNK);
    const int s   = rem / NCHUNK;
    const int c   = rem % NCHUNK;
    const int x0  = s * STRIP;
    const int y0  = c * CHUNK;

    const int  xg     = x0 + tid - 16;                 // global column for this thread
    const bool colin  = (xg >= 0 && xg < W);
    const bool active = (tid >= 16 && tid < 16 + STRIP && xg < W);

    const float* mbase = mask + (size_t)b * HW;
    const float* pbase = pred + (size_t)b * HW;

    float S3 = 0.f, S15 = 0.f, S31 = 0.f;
    float a0 = 0.f, a1 = 0.f, a2 = 0.f, a3 = 0.f, a4 = 0.f;

    // ---------------- priming: build ring [y0-17, y0+14] and S_k(y0-1) ----------------
    for (int r = y0 - 17; r <= y0 + 14; ++r) {
        float v = 0.f;
        if (r >= 0 && r < H && colin) v = mbase[r * W + xg];
        #pragma unroll
        for (int d = 1; d < 32; d <<= 1) {
            float t = __shfl_up_sync(0xffffffffu, v, d);
            if (lane >= d) v += t;
        }
        __syncthreads();                       // prior iter's smem reads complete
        if (lane == 31) wsum[warp] = v;
        __syncthreads();
        float off = 0.f;
        #pragma unroll
        for (int wq = 0; wq < 8; ++wq) if (wq < warp) off += wsum[wq];
        const int slot = (r + 64) & 31;
        Pl[slot][tid] = v + off;
        __syncthreads();
        if (active) {
            const float* P = Pl[slot];
            if (r >= y0 - 2  && r <= y0     ) S3  += P[tid + 1]  - P[tid - 2];
            if (r >= y0 - 8  && r <= y0 + 6 ) S15 += P[tid + 7]  - P[tid - 8];
            if (r >= y0 - 16 && r <= y0 + 14) S31 += P[tid + 15] - P[tid - 16];
        }
    }

    // ---------------- main loop over output rows ----------------
    for (int y = y0; y < y0 + CHUNK; ++y) {
        const int rn = y + 15;
        float v = 0.f;
        if (rn < H && colin) v = mbase[rn * W + xg];
        float pv = 0.f;
        if (active) pv = pbase[y * W + xg];

        #pragma unroll
        for (int d = 1; d < 32; d <<= 1) {
            float t = __shfl_up_sync(0xffffffffu, v, d);
            if (lane >= d) v += t;
        }
        __syncthreads();
        if (lane == 31) wsum[warp] = v;
        __syncthreads();
        float off = 0.f;
        #pragma unroll
        for (int wq = 0; wq < 8; ++wq) if (wq < warp) off += wsum[wq];
        const int slot = (rn + 64) & 31;
        Pl[slot][tid] = v + off;
        __syncthreads();

        if (active) {
            const float* Pn   = Pl[slot];
            const float* Po31 = Pl[(y - 16 + 64) & 31];
            const float* P7   = Pl[(y + 7  + 64) & 31];
            const float* Po15 = Pl[(y - 8  + 64) & 31];
            const float* P1   = Pl[(y + 1  + 64) & 31];
            const float* Po3  = Pl[(y - 2  + 64) & 31];
            const float* Py   = Pl[(y      + 64) & 31];

            S31 += (Pn[tid + 15] - Pn[tid - 16]) - (Po31[tid + 15] - Po31[tid - 16]);
            S15 += (P7[tid + 7]  - P7[tid - 8])  - (Po15[tid + 7]  - Po15[tid - 8]);
            S3  += (P1[tid + 1]  - P1[tid - 2])  - (Po3[tid + 1]   - Po3[tid - 2]);

            float m = Py[tid] - Py[tid - 1];
            float w = 1.f + 5.f * ( fabsf(S3  * (1.f / 9.f)   - m)
                                  + fabsf(S15 * (1.f / 225.f) - m)
                                  + fabsf(S31 * (1.f / 961.f) - m) );
            float x = pv;
            float e = __expf(-fabsf(x));
            float l = __logf(1.f + e);                 // log1p(exp(-|x|))
            float bce = fmaxf(x, 0.f) - x * m + l;
            float sg  = ((x >= 0.f) ? 1.f : e) / (1.f + e);  // sigmoid(x)

            a0 += w;
            a1 += w * bce;
            a2 += sg * m * w;        // inter
            a3 += (sg + m) * w;      // union
            a4 += fabsf(sg - m);     // for global mae
        }
    }

    // ---------------- block reduction + atomics ----------------
    #pragma unroll
    for (int d = 16; d > 0; d >>= 1) {
        a0 += __shfl_down_sync(0xffffffffu, a0, d);
        a1 += __shfl_down_sync(0xffffffffu, a1, d);
        a2 += __shfl_down_sync(0xffffffffu, a2, d);
        a3 += __shfl_down_sync(0xffffffffu, a3, d);
        a4 += __shfl_down_sync(0xffffffffu, a4, d);
    }
    if (lane == 0) {
        red[warp][0] = a0; red[warp][1] = a1; red[warp][2] = a2;
        red[warp][3] = a3; red[warp][4] = a4;
    }
    __syncthreads();
    if (warp == 0 && lane < 5) {
        float t = 0.f;
        #pragma unroll
        for (int wq = 0; wq < 8; ++wq) t += red[wq][lane];
        atomicAdd(&g_accum[b * 5 + lane], t);
    }
}

__global__ void finalize_kernel(float* __restrict__ out) {
    float mae_total = 0.f;
    for (int b = 0; b < BATCH; ++b) mae_total += g_accum[b * 5 + 4];
    const float mae = mae_total / (float)((long long)BATCH * HW);
    float acc = 0.f;
    for (int b = 0; b < BATCH; ++b) {
        float ws = g_accum[b * 5 + 0];
        float wb = g_accum[b * 5 + 1];
        float it = g_accum[b * 5 + 2];
        float un = g_accum[b * 5 + 3];
        float wbce = wb / ws;
        float wiou = 1.f - (it + 1.f) / (un - it + 1.f);
        float wmae = mae * ws / (ws - (float)HW);
        acc += 0.7f * (wbce + wiou + wmae);
    }
    out[0] = acc / (float)BATCH;
}

extern "C" void kernel_launch(void* const* d_in, const int* in_sizes, int n_in,
                              void* d_out, int out_size) {
    const float* pred = (const float*)d_in[0];
    const float* mask = (const float*)d_in[1];
    float* out = (float*)d_out;

    zero_kernel<<<1, 128>>>();
    adaptive_loss_main<<<BATCH * NSTRIP * NCHUNK, 256>>>(pred, mask);
    finalize_kernel<<<1, 1>>>(out);
}